// round 7
// baseline (speedup 1.0000x reference)
#include <cuda_runtime.h>
#include <math.h>

// Problem constants (fixed by the benchmark)
#define BB      8
#define NN      3072
#define T_OUT   128
#define C_IN    32
#define D_EMB   8
#define C_OUTD  64
#define NBUCK   (BB * C_IN)     // 256 buckets (b, channel)
#define BIGV    1e10f

// scanned per-(b,c,tau) sums: (S0=Z, S1=sum dw*t, S2=sum dw*v, cnt)
__device__ float4 g_acc[NBUCK * T_OUT];
// weight-only precompute: gP[q][co], q = 3*c + {0:Wd, 1:(bd+bv+emb[c]), 2:Wv}
__device__ float  g_P[96 * C_OUTD];
__device__ float  g_smax;
// grid barrier: monotonically increasing; each launch adds exactly NBUCK, so
// the counter is always a multiple of NBUCK at launch start (epoch trick:
// no reset needed -> deterministic and graph-replay safe).
__device__ unsigned int g_bar = 0;

// ---------------- Fused kernel ------------------------------------------------
// Phase A (all 256 blocks): per-(b,channel) gather + inv_density + tau scatter
//   + tau scan -> g_acc.  Block 0 additionally computes g_P / g_smax.
// Grid barrier (atomic epoch counter).
// Phase B (blocks 0..127): factorized epilogue GEMM, 8 (b,tau) rows per block.
__global__ __launch_bounds__(256) void k_fused(const float* __restrict__ x,
                                               const float* __restrict__ outpos,
                                               const float* __restrict__ ksp,
                                               const float* __restrict__ Wd,
                                               const float* __restrict__ bd,
                                               const float* __restrict__ emb,
                                               const float* __restrict__ Wv,
                                               const float* __restrict__ bv,
                                               const float* __restrict__ Wl,
                                               const float* __restrict__ bl,
                                               float* __restrict__ out) {
    const int bkt = blockIdx.x;          // 0..255
    const int b   = bkt >> 5;            // batch
    const int c   = bkt & 31;            // channel
    const int tid = threadIdx.x;         // 256 threads

    // Shared pool, reused across phases.
    // Phase A: st[3072]f @0 | sv[3072]f @12288 | spd[3072]B @24576 |
    //          spos[128]f @27648 | sacc[128]f4 @28160   (total 30208 B)
    // Phase B: sP[96][64]f @0 (24576 B) | sU[8][96]f @24576 (3072 B) |
    //          spos survives untouched @27648
    __shared__ __align__(16) char sbuf[30208];
    float*         st   = (float*)sbuf;
    float*         sv   = (float*)(sbuf + 12288);
    unsigned char* spd  = (unsigned char*)(sbuf + 24576);
    float*         spos = (float*)(sbuf + 27648);
    float4*        sacc = (float4*)(sbuf + 28160);
    __shared__ int scnt;

    if (tid == 0) scnt = 0;
    if (tid < T_OUT) {
        spos[tid] = outpos[tid];
        sacc[tid] = make_float4(0.f, 0.f, 0.f, 0.f);
    }
    __syncthreads();

    // ---- block 0 extra: weight-only precompute (coalesced float4 Wl reads) ----
    if (bkt == 0) {
        if (tid == 0) {
            float m = spos[0];
            for (int i = 1; i < T_OUT; i++) m = fmaxf(m, spos[i]);
            g_smax = m;
        }
        for (int cell = tid; cell < C_OUTD * C_IN; cell += 256) {
            int co = cell >> 5;          // 0..63
            int cc = cell & 31;          // 0..31
            const float4* w4 = (const float4*)(Wl + co * (C_IN * D_EMB) + cc * D_EMB);
            float4 wa = w4[0], wb = w4[1];
            float we[8] = {wa.x, wa.y, wa.z, wa.w, wb.x, wb.y, wb.z, wb.w};
            float p1 = 0.f, p2 = 0.f, p3 = 0.f;
            #pragma unroll
            for (int d = 0; d < D_EMB; d++) {
                p1 += Wd[d] * we[d];
                p2 += (bd[d] + bv[d] + emb[cc * D_EMB + d]) * we[d];
                p3 += Wv[d] * we[d];
            }
            g_P[(3 * cc + 0) * C_OUTD + co] = p1;
            g_P[(3 * cc + 1) * C_OUTD + co] = p2;
            g_P[(3 * cc + 2) * C_OUTD + co] = p3;
        }
    }

    // ---- Phase A: gather this block's channel points from x[b] ----
    const float* xb = x + (size_t)b * NN * 3;
    for (int i = tid; i < NN; i += 256) {
        float ff = xb[i * 3 + 0];
        if ((int)ff == c) {
            float vv = xb[i * 3 + 1];
            float tt = xb[i * 3 + 2];
            int p = atomicAdd(&scnt, 1);           // shared atomic, order irrelevant
            st[p]  = tt;
            sv[p]  = vv;
            spd[p] = (ff != 0.f || vv != 0.f || tt != 0.f) ? 1 : 0;
        }
    }
    __syncthreads();

    const int k = scnt;
    const float ks = ksp[0];

    // Pairwise min |t_p - t_j| (pd!=0 excludes self / exact duplicates),
    // then dw scatter into first causal tau bucket.
    for (int p = tid; p < k; p += 256) {
        float tp = st[p];
        float mind = BIGV;
        for (int j = 0; j < k; j++) {
            float d = fabsf(tp - st[j]);
            if (d > 0.f) mind = fminf(mind, d);
        }
        if (spd[p]) {
            float dw = powf(mind, ks);
            // lower_bound: smallest tau with pos[tau] >= tp (causal: tp <= pos)
            int lo = 0, hi = T_OUT;
            while (lo < hi) {
                int mid = (lo + hi) >> 1;
                if (spos[mid] < tp) lo = mid + 1; else hi = mid;
            }
            if (lo < T_OUT) {
                float vp = sv[p];
                atomicAdd(&sacc[lo].x, dw);
                atomicAdd(&sacc[lo].y, dw * tp);
                atomicAdd(&sacc[lo].z, dw * vp);
                atomicAdd(&sacc[lo].w, 1.f);
            }
        }
    }
    __syncthreads();

    // Inclusive scan over tau (suffix-contribution -> prefix sum).
    for (int d = 1; d < T_OUT; d <<= 1) {
        float4 v = make_float4(0.f, 0.f, 0.f, 0.f);
        if (tid < T_OUT && tid >= d) v = sacc[tid - d];
        __syncthreads();
        if (tid < T_OUT) {
            sacc[tid].x += v.x; sacc[tid].y += v.y;
            sacc[tid].z += v.z; sacc[tid].w += v.w;
        }
        __syncthreads();
    }
    if (tid < T_OUT) g_acc[bkt * T_OUT + tid] = sacc[tid];

    // ---- grid barrier (epoch counter, no reset) ----
    __threadfence();          // publish this thread's g_acc / g_P stores
    __syncthreads();          // all block stores fenced before arrive
    if (bkt >= 128) {
        if (tid == 0) atomicAdd(&g_bar, 1u);
        return;               // retire, free the SM
    }
    if (tid == 0) {
        unsigned int t = atomicAdd(&g_bar, 1u);
        unsigned int target = (t / NBUCK + 1u) * NBUCK;
        while (*(volatile unsigned int*)&g_bar < target) { __nanosleep(64); }
    }
    __syncthreads();
    __threadfence();          // acquire: order subsequent g_acc/g_P loads

    // ---- Phase B: epilogue GEMM (blocks 0..127, 8 rows each) ----
    float (*sP)[C_OUTD] = (float(*)[C_OUTD])sbuf;          // 24 KB, overlays st/sv
    float (*sU)[96]     = (float(*)[96])(sbuf + 24576);    // 3 KB, overlays spd
    // spos @27648 still holds outpos.

    // Load precomputed P (24 KB, L2-resident), coalesced float4.
    {
        const float4* src = (const float4*)g_P;
        float4* dst = (float4*)&sP[0][0];
        #pragma unroll
        for (int i = 0; i < (96 * C_OUTD / 4) / 256; i++)
            dst[tid + i * 256] = src[tid + i * 256];
    }
    // Per-row scalars u1,u2,u3: 8 rows x 32 channels = 256 threads.
    {
        float smax = g_smax;
        int r  = tid >> 5;       // row slot 0..7
        int cc = tid & 31;       // channel
        int row = blockIdx.x * 8 + r;     // row = b*T_OUT + tau
        int rb  = row >> 7;
        int tau = row & 127;
        float4 a = g_acc[(rb * C_IN + cc) * T_OUT + tau];
        float r_ = 1.f / ((a.x + 1e-10f) * (a.w + 1e-10f));
        float A  = (a.y - spos[tau] * a.x) / smax;
        sU[r][3 * cc + 0] = A   * r_;
        sU[r][3 * cc + 1] = a.x * r_;
        sU[r][3 * cc + 2] = a.z * r_;
    }
    __syncthreads();

    // (8 x 96) x (96 x 64) dot, all shared-resident.
    int co    = tid & 63;
    int rslot = tid >> 6;        // 0..3
    float blv = bl[co];
    for (int rr = rslot; rr < 8; rr += 4) {
        int row = blockIdx.x * 8 + rr;
        int rb  = row >> 7;
        int tau = row & 127;
        float acc = blv;
        #pragma unroll
        for (int q = 0; q < 96; q++)
            acc += sU[rr][q] * sP[q][co];
        out[(rb * C_OUTD + co) * T_OUT + tau] = acc;   // (B, C_OUT, T)
    }
}

// ---------------- launch ------------------------------------------------------
extern "C" void kernel_launch(void* const* d_in, const int* in_sizes, int n_in,
                              void* d_out, int out_size) {
    const float* x    = (const float*)d_in[0];  // (B,N,3)
    const float* pos  = (const float*)d_in[1];  // (T_OUT,)
    const float* Wd   = (const float*)d_in[2];  // (D_EMB,)
    const float* bd   = (const float*)d_in[3];  // (D_EMB,)
    const float* emb  = (const float*)d_in[4];  // (C_IN+1, D_EMB)
    const float* Wv   = (const float*)d_in[5];  // (D_EMB,)
    const float* bvv  = (const float*)d_in[6];  // (D_EMB,)
    const float* Wl   = (const float*)d_in[7];  // (C_OUT, D_EMB*C_IN)
    const float* bl   = (const float*)d_in[8];  // (C_OUT,)
    const float* ks   = (const float*)d_in[9];  // scalar
    float* out = (float*)d_out;

    k_fused<<<NBUCK, 256>>>(x, pos, ks, Wd, bd, emb, Wv, bvv, Wl, bl, out);
}

// round 8
// speedup vs baseline: 1.2429x; 1.2429x over previous
#include <cuda_runtime.h>
#include <math.h>

// Problem constants (fixed by the benchmark)
#define BB      8
#define NN      3072
#define T_OUT   128
#define C_IN    32
#define D_EMB   8
#define C_OUTD  64
#define NBUCK   (BB * C_IN)     // 256 buckets (b, channel)
#define NROW    (BB * T_OUT)    // 1024 output rows
#define BIGV    1e10f

// g_U[q][row]: per-row GEMM scalars, q = 3*c + {0,1,2}, row = b*128+tau
__device__ __align__(16) float g_U[96 * NROW];
// g_P[q][co]: weight-only precompute
__device__ __align__(16) float g_P[96 * C_OUTD];

// ---------------- Kernel A ----------------------------------------------------
// Blocks 0..255: per-(b,channel) gather + inv_density + tau scatter + scan +
//   direct U emission. Block 256: weight precompute -> g_P.
__global__ __launch_bounds__(256) void kA(const float* __restrict__ x,
                                          const float* __restrict__ outpos,
                                          const float* __restrict__ ksp,
                                          const float* __restrict__ Wd,
                                          const float* __restrict__ bd,
                                          const float* __restrict__ emb,
                                          const float* __restrict__ Wv,
                                          const float* __restrict__ bv,
                                          const float* __restrict__ Wl) {
    const int bkt  = blockIdx.x;
    const int tid  = threadIdx.x;
    const int lane = tid & 31;
    const int wid  = tid >> 5;

    if (bkt == NBUCK) {
        // ---- weight-only precompute (coalesced float4 Wl reads) ----
        for (int cell = tid; cell < C_OUTD * C_IN; cell += 256) {
            int co = cell >> 5;          // 0..63
            int cc = cell & 31;          // 0..31
            const float4* w4 = (const float4*)(Wl + co * (C_IN * D_EMB) + cc * D_EMB);
            float4 wa = w4[0], wb = w4[1];
            float we[8] = {wa.x, wa.y, wa.z, wa.w, wb.x, wb.y, wb.z, wb.w};
            float p1 = 0.f, p2 = 0.f, p3 = 0.f;
            #pragma unroll
            for (int d = 0; d < D_EMB; d++) {
                p1 += Wd[d] * we[d];
                p2 += (bd[d] + bv[d] + emb[cc * D_EMB + d]) * we[d];
                p3 += Wv[d] * we[d];
            }
            g_P[(3 * cc + 0) * C_OUTD + co] = p1;
            g_P[(3 * cc + 1) * C_OUTD + co] = p2;
            g_P[(3 * cc + 2) * C_OUTD + co] = p3;
        }
        return;
    }

    const int b = bkt >> 5;              // batch
    const int c = bkt & 31;              // channel

    __shared__ float  st[NN];            // t of matching points
    __shared__ float  sv[NN];            // v of matching points
    __shared__ unsigned char spd[NN];    // padding flag
    __shared__ float  spos[T_OUT];
    __shared__ float4 sacc[T_OUT];
    __shared__ float4 swsum[4];
    __shared__ float  ssmax;
    __shared__ int    scnt;

    if (tid == 0) scnt = 0;
    if (tid < T_OUT) {
        spos[tid] = outpos[tid];
        sacc[tid] = make_float4(0.f, 0.f, 0.f, 0.f);
    }
    __syncthreads();

    // smax over outpos (warp 0)
    if (wid == 0) {
        float m = fmaxf(fmaxf(spos[lane], spos[lane + 32]),
                        fmaxf(spos[lane + 64], spos[lane + 96]));
        #pragma unroll
        for (int o = 16; o > 0; o >>= 1)
            m = fmaxf(m, __shfl_xor_sync(0xffffffffu, m, o));
        if (lane == 0) ssmax = m;
    }

    // ---- two-pass ballot-compaction gather (8 shared atomics per block) ----
    const float* xb = x + (size_t)b * NN * 3;
    unsigned ball[NN / 256];
    int tot = 0;
    #pragma unroll
    for (int it = 0; it < NN / 256; it++) {
        int i = tid + it * 256;
        float ff = xb[i * 3];
        unsigned m = __ballot_sync(0xffffffffu, (int)ff == c);
        ball[it] = m;
        tot += __popc(m);
    }
    unsigned wbase = 0;
    if (lane == 0) wbase = (unsigned)atomicAdd(&scnt, tot);
    wbase = __shfl_sync(0xffffffffu, wbase, 0);
    int wo = 0;
    #pragma unroll
    for (int it = 0; it < NN / 256; it++) {
        int i = tid + it * 256;
        unsigned m = ball[it];
        if ((m >> lane) & 1u) {
            float vv = xb[i * 3 + 1];
            float tt = xb[i * 3 + 2];
            int p = (int)wbase + wo + __popc(m & ((1u << lane) - 1u));
            st[p]  = tt;
            sv[p]  = vv;
            // within bucket f==c: if c!=0, point is never all-zero
            spd[p] = (c != 0) || (vv != 0.f) || (tt != 0.f);
        }
        wo += __popc(m);
    }
    __syncthreads();

    const int k = scnt;
    const float ks = ksp[0];

    // ---- pairwise min |t_p - t_j| + dw scatter into first causal tau ----
    for (int p = tid; p < k; p += 256) {
        float tp = st[p];
        float mind = BIGV;
        for (int j = 0; j < k; j++) {
            float d = fabsf(tp - st[j]);
            if (d > 0.f) mind = fminf(mind, d);
        }
        if (spd[p]) {
            float dw = powf(mind, ks);
            int lo = 0, hi = T_OUT;
            while (lo < hi) {
                int mid = (lo + hi) >> 1;
                if (spos[mid] < tp) lo = mid + 1; else hi = mid;
            }
            if (lo < T_OUT) {
                float vp = sv[p];
                atomicAdd(&sacc[lo].x, dw);
                atomicAdd(&sacc[lo].y, dw * tp);
                atomicAdd(&sacc[lo].z, dw * vp);
                atomicAdd(&sacc[lo].w, 1.f);
            }
        }
    }
    __syncthreads();

    // ---- warp-shuffle inclusive scan over tau, then emit U directly ----
    if (tid < T_OUT) {
        float4 a = sacc[tid];
        #pragma unroll
        for (int o = 1; o < 32; o <<= 1) {
            float x0 = __shfl_up_sync(0xffffffffu, a.x, o);
            float y0 = __shfl_up_sync(0xffffffffu, a.y, o);
            float z0 = __shfl_up_sync(0xffffffffu, a.z, o);
            float w0 = __shfl_up_sync(0xffffffffu, a.w, o);
            if (lane >= o) { a.x += x0; a.y += y0; a.z += z0; a.w += w0; }
        }
        if (lane == 31) swsum[wid] = a;
        __syncthreads();
        float4 add = make_float4(0.f, 0.f, 0.f, 0.f);
        for (int w = 0; w < wid; w++) {
            float4 s = swsum[w];
            add.x += s.x; add.y += s.y; add.z += s.z; add.w += s.w;
        }
        float S0 = a.x + add.x, S1 = a.y + add.y;
        float S2 = a.z + add.z, cnt = a.w + add.w;
        float r_ = 1.f / ((S0 + 1e-10f) * (cnt + 1e-10f));
        float A  = (S1 - spos[tid] * S0) / ssmax;
        int rowbase = b * T_OUT + tid;
        g_U[(3 * c + 0) * NROW + rowbase] = A  * r_;
        g_U[(3 * c + 1) * NROW + rowbase] = S0 * r_;
        g_U[(3 * c + 2) * NROW + rowbase] = S2 * r_;
    } else {
        __syncthreads();
    }
}

// ---------------- Kernel B: register-tiled epilogue GEMM -----------------------
// out[b,co,tau] = bl[co] + sum_q U[q][row] * P[q][co]
// 64 blocks x 16 rows; thread owns (co, 4 consecutive rows).
__global__ __launch_bounds__(256) void kB(const float* __restrict__ bl,
                                          float* __restrict__ out) {
    __shared__ __align__(16) float sP[96 * C_OUTD];   // 24 KB
    __shared__ __align__(16) float sUT[96 * 24];      // 9 KB (16 rows + pad to 24)
    const int tid  = threadIdx.x;
    const int row0 = blockIdx.x * 16;

    // load P (coalesced float4)
    {
        const float4* src = (const float4*)g_P;
        float4* dst = (float4*)sP;
        #pragma unroll
        for (int i = 0; i < 6; i++)
            dst[tid + i * 256] = src[tid + i * 256];
    }
    // load U slab transposed: sUT[q][r], r in 0..15 (row-padded to 24)
    for (int i = tid; i < 96 * 4; i += 256) {
        int q  = i >> 2;
        int rq = i & 3;
        float4 u = *(const float4*)(g_U + q * NROW + row0 + rq * 4);
        *(float4*)(sUT + q * 24 + rq * 4) = u;
    }
    __syncthreads();

    const int co = tid & 63;
    const int rg = tid >> 6;     // 0..3, 4 rows each
    float a0 = 0.f, a1 = 0.f, a2 = 0.f, a3 = 0.f;
    #pragma unroll 8
    for (int q = 0; q < 96; q++) {
        float p = sP[q * C_OUTD + co];
        float4 u = *(const float4*)(sUT + q * 24 + rg * 4);
        a0 += u.x * p; a1 += u.y * p; a2 += u.z * p; a3 += u.w * p;
    }
    float blv = bl[co];
    int row = row0 + rg * 4;          // 4 consecutive taus, same b
    int b   = row >> 7;
    int tau = row & 127;
    float4 o4 = make_float4(a0 + blv, a1 + blv, a2 + blv, a3 + blv);
    *(float4*)(out + ((size_t)(b * C_OUTD + co)) * T_OUT + tau) = o4;
}

// ---------------- launch ------------------------------------------------------
extern "C" void kernel_launch(void* const* d_in, const int* in_sizes, int n_in,
                              void* d_out, int out_size) {
    const float* x    = (const float*)d_in[0];  // (B,N,3)
    const float* pos  = (const float*)d_in[1];  // (T_OUT,)
    const float* Wd   = (const float*)d_in[2];  // (D_EMB,)
    const float* bd   = (const float*)d_in[3];  // (D_EMB,)
    const float* emb  = (const float*)d_in[4];  // (C_IN+1, D_EMB)
    const float* Wv   = (const float*)d_in[5];  // (D_EMB,)
    const float* bvv  = (const float*)d_in[6];  // (D_EMB,)
    const float* Wl   = (const float*)d_in[7];  // (C_OUT, D_EMB*C_IN)
    const float* bl   = (const float*)d_in[8];  // (C_OUT,)
    const float* ks   = (const float*)d_in[9];  // scalar
    float* out = (float*)d_out;

    kA<<<NBUCK + 1, 256>>>(x, pos, ks, Wd, bd, emb, Wv, bvv, Wl);
    kB<<<NROW / 16, 256>>>(bl, out);
}